// round 2
// baseline (speedup 1.0000x reference)
#include <cuda_runtime.h>
#include <cstdint>
#include <math.h>

typedef unsigned int u32;

#define NROWS 8192
#define DCOLS 1024
#define KDIM  8192

// ---------------- scratch (static __device__, no allocation) ----------------
__device__ float g_support[(size_t)NROWS * DCOLS];
__device__ float g_posA[(size_t)NROWS * DCOLS];
__device__ float g_posB[(size_t)NROWS * DCOLS];
__device__ unsigned g_mm[2];

// ---------------- threefry2x32 (JAX-exact) ----------------
__device__ __forceinline__ void dtf(u32 k0, u32 k1, u32 x0, u32 x1, u32& o0, u32& o1) {
    u32 ks2 = k0 ^ k1 ^ 0x1BD11BDAu;
    x0 += k0; x1 += k1;
#define TFROUND(r) { x0 += x1; x1 = __funnelshift_l(x1, x1, (r)); x1 ^= x0; }
    TFROUND(13) TFROUND(15) TFROUND(26) TFROUND(6)
    x0 += k1;  x1 += ks2 + 1u;
    TFROUND(17) TFROUND(29) TFROUND(16) TFROUND(24)
    x0 += ks2; x1 += k0 + 2u;
    TFROUND(13) TFROUND(15) TFROUND(26) TFROUND(6)
    x0 += k0;  x1 += k1 + 3u;
    TFROUND(17) TFROUND(29) TFROUND(16) TFROUND(24)
    x0 += k1;  x1 += ks2 + 4u;
    TFROUND(13) TFROUND(15) TFROUND(26) TFROUND(6)
    x0 += ks2; x1 += k0 + 5u;
#undef TFROUND
    o0 = x0; o1 = x1;
}

static void htf(u32 k0, u32 k1, u32 x0, u32 x1, u32* o0, u32* o1) {
    u32 ks[3] = {k0, k1, k0 ^ k1 ^ 0x1BD11BDAu};
    static const int R0[4] = {13, 15, 26, 6};
    static const int R1[4] = {17, 29, 16, 24};
    x0 += ks[0]; x1 += ks[1];
    for (int i = 0; i < 5; i++) {
        const int* R = (i & 1) ? R1 : R0;
        for (int j = 0; j < 4; j++) {
            x0 += x1;
            x1 = (x1 << R[j]) | (x1 >> (32 - R[j]));
            x1 ^= x0;
        }
        x0 += ks[(i + 1) % 3];
        x1 += ks[(i + 2) % 3] + (u32)(i + 1);
    }
    *o0 = x0; *o1 = x1;
}

// partitionable threefry 32-bit random bits: element e -> xor of PRF output words
__device__ __forceinline__ u32 dbits32(u32 k0, u32 k1, u32 e) {
    u32 o0, o1;
    dtf(k0, k1, 0u, e, o0, o1);
    return o0 ^ o1;
}
static u32 hbits32(u32 k0, u32 k1, u32 e) {
    u32 o0, o1;
    htf(k0, k1, 0u, e, &o0, &o1);
    return o0 ^ o1;
}

// jax uniform: bitcast(bits>>9 | 0x3f800000) - 1.0
__device__ __forceinline__ float bits01(u32 b) {
    return __uint_as_float((b >> 9) | 0x3f800000u) - 1.0f;
}

// monotonic float<->uint mapping for atomic min/max
__device__ __forceinline__ u32 f2key(float f) {
    u32 b = __float_as_uint(f);
    return (b & 0x80000000u) ? ~b : (b | 0x80000000u);
}
__device__ __forceinline__ float key2f(u32 k) {
    return __uint_as_float((k & 0x80000000u) ? (k ^ 0x80000000u) : ~k);
}

// ---------------- kernels ----------------
__global__ void init_mm_kernel() {
    g_mm[0] = 0xFFFFFFFFu;  // min accumulator (mapped space)
    g_mm[1] = 0u;           // max accumulator
}

__global__ void __launch_bounds__(256) minmax_kernel() {
    u32 lmin = 0xFFFFFFFFu, lmax = 0u;
    const size_t n = (size_t)NROWS * DCOLS;
    for (size_t idx = (size_t)blockIdx.x * blockDim.x + threadIdx.x; idx < n;
         idx += (size_t)gridDim.x * blockDim.x) {
        u32 k = f2key(g_support[idx]);
        lmin = min(lmin, k);
        lmax = max(lmax, k);
    }
#pragma unroll
    for (int o = 16; o > 0; o >>= 1) {
        lmin = min(lmin, __shfl_xor_sync(0xffffffffu, lmin, o));
        lmax = max(lmax, __shfl_xor_sync(0xffffffffu, lmax, o));
    }
    __shared__ u32 smin[8], smax[8];
    int w = threadIdx.x >> 5, l = threadIdx.x & 31;
    if (l == 0) { smin[w] = lmin; smax[w] = lmax; }
    __syncthreads();
    if (threadIdx.x == 0) {
        u32 m0 = smin[0], m1 = smax[0];
        for (int q = 1; q < 8; q++) { m0 = min(m0, smin[q]); m1 = max(m1, smax[q]); }
        atomicMin(&g_mm[0], m0);
        atomicMax(&g_mm[1], m1);
    }
}

// classic 128x128x8 SGEMM, 256 threads, 8x8 per thread; fused epilogues.
// mode 0: D0 = D1 = (1-alpha)*acc + alpha*Caux     (Caux=h0, scal=alpha)
// mode 1: D0 = theta*acc + (1-theta)*Caux          (Caux=support, scal=lamda, lptr=l)
__global__ void __launch_bounds__(256) sgemm_kernel(
    const float* __restrict__ A, const float* __restrict__ B,
    int M, int N, int K, int mode,
    const float* __restrict__ Caux,
    float* __restrict__ D0, float* __restrict__ D1,
    const float* __restrict__ scal, const int* __restrict__ lptr)
{
    __shared__ float As[8][128];
    __shared__ float Bs[8][128];
    const int tid = threadIdx.x;
    const int tx = tid & 15, ty = tid >> 4;
    const int rowBase = blockIdx.y * 128;
    const int colBase = blockIdx.x * 128;

    float acc[8][8];
#pragma unroll
    for (int i = 0; i < 8; i++)
#pragma unroll
        for (int j = 0; j < 8; j++) acc[i][j] = 0.0f;

    const int ar = tid >> 1;         // 0..127 (A tile row)
    const int ah = (tid & 1) << 2;   // 0 or 4 (A tile col group)
    const int br = tid >> 5;         // 0..7   (B tile row)
    const int bc = (tid & 31) << 2;  // 0..124 (B tile col)

    for (int k0 = 0; k0 < K; k0 += 8) {
        float4 av = *reinterpret_cast<const float4*>(&A[(size_t)(rowBase + ar) * K + k0 + ah]);
        float4 bv = *reinterpret_cast<const float4*>(&B[(size_t)(k0 + br) * N + colBase + bc]);
        As[ah + 0][ar] = av.x;
        As[ah + 1][ar] = av.y;
        As[ah + 2][ar] = av.z;
        As[ah + 3][ar] = av.w;
        *reinterpret_cast<float4*>(&Bs[br][bc]) = bv;
        __syncthreads();
#pragma unroll
        for (int kk = 0; kk < 8; kk++) {
            float4 a0 = *reinterpret_cast<const float4*>(&As[kk][ty * 8]);
            float4 a1 = *reinterpret_cast<const float4*>(&As[kk][ty * 8 + 4]);
            float4 b0 = *reinterpret_cast<const float4*>(&Bs[kk][tx * 8]);
            float4 b1 = *reinterpret_cast<const float4*>(&Bs[kk][tx * 8 + 4]);
            float ra[8] = {a0.x, a0.y, a0.z, a0.w, a1.x, a1.y, a1.z, a1.w};
            float rb[8] = {b0.x, b0.y, b0.z, b0.w, b1.x, b1.y, b1.z, b1.w};
#pragma unroll
            for (int i = 0; i < 8; i++)
#pragma unroll
                for (int j = 0; j < 8; j++)
                    acc[i][j] += ra[i] * rb[j];
        }
        __syncthreads();
    }

    if (mode == 0) {
        const float alpha = *scal;
        const float oma = 1.0f - alpha;
#pragma unroll
        for (int i = 0; i < 8; i++) {
            int r = rowBase + ty * 8 + i;
#pragma unroll
            for (int j = 0; j < 8; j++) {
                int c = colBase + tx * 8 + j;
                size_t off = (size_t)r * N + c;
                float s = oma * acc[i][j] + alpha * Caux[off];
                D0[off] = s;
                D1[off] = s;
            }
        }
    } else {
        const float lam = *scal;
        const float lv = (float)(*lptr);
        const float theta = logf(lam / lv + 1.0f);
        const float omt = 1.0f - theta;
#pragma unroll
        for (int i = 0; i < 8; i++) {
            int r = rowBase + ty * 8 + i;
#pragma unroll
            for (int j = 0; j < 8; j++) {
                int c = colBase + tx * 8 + j;
                size_t off = (size_t)r * N + c;
                D0[off] = theta * acc[i][j] + omt * Caux[off];
            }
        }
    }
}

// one block per agent row; 256 threads x 4 cols
__global__ void __launch_bounds__(256) whale_kernel(
    const float* __restrict__ posIn, float* __restrict__ posOut,
    int leaderIdx, float av, float twoa, float a2m1,
    u32 k1a, u32 k1b, u32 k2a, u32 k2b, u32 k3a, u32 k3b, u32 k4a, u32 k4b,
    u32 kba, u32 kbb)
{
    const int i = blockIdx.x;
    const int t = threadIdx.x;
    __shared__ float sh[4];
    if (t < 4) {
        u32 ka, kb;
        if (t == 0)      { ka = k1a; kb = k1b; }
        else if (t == 1) { ka = k2a; kb = k2b; }
        else if (t == 2) { ka = k3a; kb = k3b; }
        else             { ka = k4a; kb = k4b; }
        // partitionable random_bits: element i -> xor of threefry(key, 0, i)
        sh[t] = bits01(dbits32(ka, kb, (u32)i));
    }
    __syncthreads();
    const float r1 = sh[0], r2 = sh[1], u3 = sh[2], p = sh[3];
    // strict (no-FMA) arithmetic on predicate-feeding values, matching XLA
    const float A  = __fsub_rn(__fmul_rn(twoa, r1), av);
    const float C  = 2.0f * r2;
    const float lp = __fadd_rn(__fmul_rn(a2m1, u3), 1.0f);
    const float lower = key2f(g_mm[0]);
    const float upper = key2f(g_mm[1]);
    const int mode = (p < 0.5f) ? ((fabsf(A) >= 1.0f) ? 0 : 1) : 2;

    const int j0 = t * 4;
    const float4 pv  = *reinterpret_cast<const float4*>(&posIn[(size_t)i * DCOLS + j0]);
    const float4 lv4 = *reinterpret_cast<const float4*>(&posIn[(size_t)leaderIdx * DCOLS + j0]);
    float pos[4] = {pv.x, pv.y, pv.z, pv.w};
    float led[4] = {lv4.x, lv4.y, lv4.z, lv4.w};
    float outv[4];

    if (mode == 0) {
        // explore: random row index per (i,j): ridx = lower_bits & 8191
#pragma unroll
        for (int q = 0; q < 4; q++) {
            u32 m = (u32)i * 1024u + (u32)(j0 + q);
            u32 bits = dbits32(kba, kbb, m);
            int ridx = (int)(bits & 8191u);
            float xr = __ldg(&posIn[(size_t)ridx * DCOLS + j0 + q]);
            outv[q] = fabsf(xr - A * fabsf(C * xr - pos[q]));
        }
    } else if (mode == 1) {
#pragma unroll
        for (int q = 0; q < 4; q++)
            outv[q] = fabsf(led[q] - A * fabsf(C * led[q] - pos[q]));
    } else {
        const float sp = expf(lp) * cosf(6.283185307179586f * lp);
#pragma unroll
        for (int q = 0; q < 4; q++)
            outv[q] = fabsf(fabsf(led[q] - pos[q]) * sp + led[q]);
    }
    float4 ov;
    ov.x = fminf(fmaxf(outv[0], lower), upper);
    ov.y = fminf(fmaxf(outv[1], lower), upper);
    ov.z = fminf(fmaxf(outv[2], lower), upper);
    ov.w = fminf(fmaxf(outv[3], lower), upper);
    *reinterpret_cast<float4*>(&posOut[(size_t)i * DCOLS + j0]) = ov;
}

// ---------------- host ----------------
extern "C" void kernel_launch(void* const* d_in, const int* in_sizes, int n_in,
                              void* d_out, int out_size) {
    (void)in_sizes; (void)n_in; (void)out_size;
    const float* input  = (const float*)d_in[0];
    const float* adj    = (const float*)d_in[1];
    const float* h0     = (const float*)d_in[2];
    const float* weight = (const float*)d_in[3];
    const float* lamda  = (const float*)d_in[4];
    const float* alpha  = (const float*)d_in[5];
    const int*   lint   = (const int*)d_in[6];
    float* out = (float*)d_out;

    float *support, *posA, *posB;
    cudaGetSymbolAddress((void**)&support, g_support);
    cudaGetSymbolAddress((void**)&posA, g_posA);
    cudaGetSymbolAddress((void**)&posB, g_posB);

    init_mm_kernel<<<1, 1>>>();

    dim3 gemm_grid(DCOLS / 128, NROWS / 128);
    // support/posA = (1-alpha)*(adj@input) + alpha*h0
    sgemm_kernel<<<gemm_grid, 256>>>(adj, input, NROWS, DCOLS, KDIM, 0,
                                     h0, support, posA, alpha, nullptr);
    minmax_kernel<<<512, 256>>>();

    // ---- JAX RNG derivation for key(42), partitionable-threefry semantics ----
    const u32 B0 = 0u, B1 = 42u;
    // split(key, 2) fold-like: subkey_j = threefry(key, 0, j)
    u32 K00, K01, L0, L1;
    htf(B0, B1, 0u, 0u, &K00, &K01);  // k0
    htf(B0, B1, 0u, 1u, &L0, &L1);    // loop_key
    // initial leader = randint(k0,(),0,8192): lower_key = split(k0)[1], bits = xor-fold
    u32 lka, lkb;
    htf(K00, K01, 0u, 1u, &lka, &lkb);
    int leader = (int)(hbits32(lka, lkb, 0u) & 8191u);

    float* pin = posA;
    float* pout = posB;
    for (int it = 0; it < 10; it++) {
        u32 f0, f1;
        htf(L0, L1, 0u, (u32)it, &f0, &f1);  // fold_in(loop_key, it)
        // split(k, 6) fold-like: subkey_j = threefry(f, 0, j)
        u32 SK[6][2];
        for (int j = 0; j < 6; j++) htf(f0, f1, 0u, (u32)j, &SK[j][0], &SK[j][1]);
        u32 k1a = SK[0][0], k1b = SK[0][1];
        u32 k2a = SK[1][0], k2b = SK[1][1];
        u32 k3a = SK[2][0], k3b = SK[2][1];
        u32 k4a = SK[3][0], k4b = SK[3][1];
        u32 k5a = SK[4][0], k5b = SK[4][1];
        u32 k6a = SK[5][0], k6b = SK[5][1];
        // ridx lower-bit key: split(k5, 2)[1]
        u32 kba, kbb;
        htf(k5a, k5b, 0u, 1u, &kba, &kbb);
        // next leader: split(k6, 2)[1] -> element-0 bits
        u32 l6a, l6b;
        htf(k6a, k6b, 0u, 1u, &l6a, &l6b);
        int nextLeader = (int)(hbits32(l6a, l6b, 0u) & 8191u);

        const float itf = (float)it;
        volatile float tmul = itf * 0.2f;          // block host FMA contraction
        const float a = 2.0f - tmul;
        const float twoa = 2.0f * a;
        volatile float tmul2 = itf * (-0.1f);
        const float a2 = -1.0f + tmul2;
        const float a2m1 = a2 - 1.0f;

        whale_kernel<<<NROWS, 256>>>(pin, pout, leader, a, twoa, a2m1,
                                     k1a, k1b, k2a, k2b, k3a, k3b, k4a, k4b,
                                     kba, kbb);
        leader = nextLeader;
        float* tswap = pin; pin = pout; pout = tswap;
    }
    // after 10 iters final positions are back in posA (== pin)

    // out = theta*(pos@weight) + (1-theta)*support
    sgemm_kernel<<<gemm_grid, 256>>>(pin, weight, NROWS, DCOLS, DCOLS, 1,
                                     support, out, nullptr, lamda, lint);
}

// round 3
// speedup vs baseline: 2.7869x; 2.7869x over previous
#include <cuda_runtime.h>
#include <cstdint>
#include <math.h>

typedef unsigned int u32;

#define NROWS 8192
#define DCOLS 1024
#define KDIM  8192

#define BM 128
#define BN 128
#define BK 16
#define AS_STRIDE 20      // 16 + 4 pad (conflict-free for A frag reads)
#define BS_STRIDE 136     // 128 + 8 pad (conflict-free for B frag reads)
#define AS_STAGE (BM * AS_STRIDE)   // 2560 floats
#define BS_STAGE (BK * BS_STRIDE)   // 2176 floats

// ---------------- scratch (static __device__, no allocation) ----------------
__device__ float g_support[(size_t)NROWS * DCOLS];
__device__ float g_posA[(size_t)NROWS * DCOLS];
__device__ float g_posB[(size_t)NROWS * DCOLS];
__device__ unsigned g_mm[2];

// ---------------- threefry2x32 (JAX-exact) ----------------
__device__ __forceinline__ void dtf(u32 k0, u32 k1, u32 x0, u32 x1, u32& o0, u32& o1) {
    u32 ks2 = k0 ^ k1 ^ 0x1BD11BDAu;
    x0 += k0; x1 += k1;
#define TFROUND(r) { x0 += x1; x1 = __funnelshift_l(x1, x1, (r)); x1 ^= x0; }
    TFROUND(13) TFROUND(15) TFROUND(26) TFROUND(6)
    x0 += k1;  x1 += ks2 + 1u;
    TFROUND(17) TFROUND(29) TFROUND(16) TFROUND(24)
    x0 += ks2; x1 += k0 + 2u;
    TFROUND(13) TFROUND(15) TFROUND(26) TFROUND(6)
    x0 += k0;  x1 += k1 + 3u;
    TFROUND(17) TFROUND(29) TFROUND(16) TFROUND(24)
    x0 += k1;  x1 += ks2 + 4u;
    TFROUND(13) TFROUND(15) TFROUND(26) TFROUND(6)
    x0 += ks2; x1 += k0 + 5u;
#undef TFROUND
    o0 = x0; o1 = x1;
}

static void htf(u32 k0, u32 k1, u32 x0, u32 x1, u32* o0, u32* o1) {
    u32 ks[3] = {k0, k1, k0 ^ k1 ^ 0x1BD11BDAu};
    static const int R0[4] = {13, 15, 26, 6};
    static const int R1[4] = {17, 29, 16, 24};
    x0 += ks[0]; x1 += ks[1];
    for (int i = 0; i < 5; i++) {
        const int* R = (i & 1) ? R1 : R0;
        for (int j = 0; j < 4; j++) {
            x0 += x1;
            x1 = (x1 << R[j]) | (x1 >> (32 - R[j]));
            x1 ^= x0;
        }
        x0 += ks[(i + 1) % 3];
        x1 += ks[(i + 2) % 3] + (u32)(i + 1);
    }
    *o0 = x0; *o1 = x1;
}

__device__ __forceinline__ u32 dbits32(u32 k0, u32 k1, u32 e) {
    u32 o0, o1;
    dtf(k0, k1, 0u, e, o0, o1);
    return o0 ^ o1;
}
static u32 hbits32(u32 k0, u32 k1, u32 e) {
    u32 o0, o1;
    htf(k0, k1, 0u, e, &o0, &o1);
    return o0 ^ o1;
}

__device__ __forceinline__ float bits01(u32 b) {
    return __uint_as_float((b >> 9) | 0x3f800000u) - 1.0f;
}

__device__ __forceinline__ u32 f2key(float f) {
    u32 b = __float_as_uint(f);
    return (b & 0x80000000u) ? ~b : (b | 0x80000000u);
}
__device__ __forceinline__ float key2f(u32 k) {
    return __uint_as_float((k & 0x80000000u) ? (k ^ 0x80000000u) : ~k);
}

// ---------------- mma / cp.async helpers ----------------
__device__ __forceinline__ u32 f2tf32(float x) {
    u32 r;
    asm("cvt.rna.tf32.f32 %0, %1;" : "=r"(r) : "f"(x));
    return r;
}

__device__ __forceinline__ void mma_tf32(float* d, const u32* a, const u32* b) {
    asm volatile(
        "mma.sync.aligned.m16n8k8.row.col.f32.tf32.tf32.f32 "
        "{%0,%1,%2,%3}, {%4,%5,%6,%7}, {%8,%9}, {%0,%1,%2,%3};"
        : "+f"(d[0]), "+f"(d[1]), "+f"(d[2]), "+f"(d[3])
        : "r"(a[0]), "r"(a[1]), "r"(a[2]), "r"(a[3]), "r"(b[0]), "r"(b[1]));
}

__device__ __forceinline__ void cp_async16(float* smem_dst, const float* gsrc) {
    u32 sa = (u32)__cvta_generic_to_shared(smem_dst);
    asm volatile("cp.async.cg.shared.global [%0], [%1], 16;\n" :: "r"(sa), "l"(gsrc));
}
__device__ __forceinline__ void cp_commit() {
    asm volatile("cp.async.commit_group;\n");
}
__device__ __forceinline__ void cp_wait0() {
    asm volatile("cp.async.wait_group 0;\n");
}

// ---------------- kernels ----------------
__global__ void init_mm_kernel() {
    g_mm[0] = 0xFFFFFFFFu;
    g_mm[1] = 0u;
}

__global__ void __launch_bounds__(256) minmax_kernel() {
    u32 lmin = 0xFFFFFFFFu, lmax = 0u;
    const size_t n = (size_t)NROWS * DCOLS;
    for (size_t idx = (size_t)blockIdx.x * blockDim.x + threadIdx.x; idx < n;
         idx += (size_t)gridDim.x * blockDim.x) {
        u32 k = f2key(g_support[idx]);
        lmin = min(lmin, k);
        lmax = max(lmax, k);
    }
#pragma unroll
    for (int o = 16; o > 0; o >>= 1) {
        lmin = min(lmin, __shfl_xor_sync(0xffffffffu, lmin, o));
        lmax = max(lmax, __shfl_xor_sync(0xffffffffu, lmax, o));
    }
    __shared__ u32 smin[8], smax[8];
    int w = threadIdx.x >> 5, l = threadIdx.x & 31;
    if (l == 0) { smin[w] = lmin; smax[w] = lmax; }
    __syncthreads();
    if (threadIdx.x == 0) {
        u32 m0 = smin[0], m1 = smax[0];
        for (int q = 1; q < 8; q++) { m0 = min(m0, smin[q]); m1 = max(m1, smax[q]); }
        atomicMin(&g_mm[0], m0);
        atomicMax(&g_mm[1], m1);
    }
}

// TF32 tensor-core GEMM: 128x128 block tile, BK=16, 2-stage cp.async pipeline,
// 8 warps of 64x32 warp tiles via m16n8k8.
// mode 0: D0 = D1 = (1-alpha)*acc + alpha*Caux     (Caux=h0, scal=alpha)
// mode 1: D0 = theta*acc + (1-theta)*Caux          (Caux=support, scal=lamda, lptr=l)
__global__ void __launch_bounds__(256, 2) mma_gemm_kernel(
    const float* __restrict__ A, const float* __restrict__ B,
    int N, int K, int mode,
    const float* __restrict__ Caux,
    float* __restrict__ D0, float* __restrict__ D1,
    const float* __restrict__ scal, const int* __restrict__ lptr)
{
    __shared__ float As[2][AS_STAGE];
    __shared__ float Bs[2][BS_STAGE];

    const int tid = threadIdx.x;
    const int lane = tid & 31;
    const int warp = tid >> 5;
    const int wm = (warp & 1) * 64;   // warp M offset within block tile
    const int wn = (warp >> 1) * 32;  // warp N offset within block tile
    const int rowBase = blockIdx.y * BM;
    const int colBase = blockIdx.x * BN;

    const int lg = lane >> 2;   // 0..7
    const int lr = lane & 3;    // 0..3

    float acc[4][4][4];
#pragma unroll
    for (int mt = 0; mt < 4; mt++)
#pragma unroll
        for (int nt = 0; nt < 4; nt++)
#pragma unroll
            for (int r = 0; r < 4; r++) acc[mt][nt][r] = 0.0f;

    // ---- stage loader: 2 A-chunks + 2 B-chunks (16B each) per thread ----
#define LOAD_STAGE(S, K0)                                                        \
    {                                                                            \
        _Pragma("unroll")                                                        \
        for (int q = 0; q < 2; q++) {                                            \
            int ch = tid + 256 * q;                                              \
            int r = ch >> 2, cc = (ch & 3) << 2;                                 \
            cp_async16(&As[S][r * AS_STRIDE + cc],                               \
                       &A[(size_t)(rowBase + r) * K + (K0) + cc]);               \
        }                                                                        \
        _Pragma("unroll")                                                        \
        for (int q = 0; q < 2; q++) {                                            \
            int ch = tid + 256 * q;                                              \
            int kk = ch >> 5, nn = (ch & 31) << 2;                               \
            cp_async16(&Bs[S][kk * BS_STRIDE + nn],                              \
                       &B[(size_t)((K0) + kk) * N + colBase + nn]);              \
        }                                                                        \
        cp_commit();                                                             \
    }

    LOAD_STAGE(0, 0)
    int s = 0;
    for (int k0 = 0; k0 < K; k0 += BK) {
        cp_wait0();
        __syncthreads();
        if (k0 + BK < K) LOAD_STAGE(s ^ 1, k0 + BK)

        const float* __restrict__ as = As[s];
        const float* __restrict__ bs = Bs[s];
#pragma unroll
        for (int ks = 0; ks < 2; ks++) {
            const int kb = ks * 8;
            u32 af[4][4], bf[4][2];
#pragma unroll
            for (int mt = 0; mt < 4; mt++) {
                int r0 = (wm + mt * 16 + lg) * AS_STRIDE + kb + lr;
                af[mt][0] = f2tf32(as[r0]);
                af[mt][1] = f2tf32(as[r0 + 8 * AS_STRIDE]);
                af[mt][2] = f2tf32(as[r0 + 4]);
                af[mt][3] = f2tf32(as[r0 + 8 * AS_STRIDE + 4]);
            }
#pragma unroll
            for (int nt = 0; nt < 4; nt++) {
                int c0 = (kb + lr) * BS_STRIDE + wn + nt * 8 + lg;
                bf[nt][0] = f2tf32(bs[c0]);
                bf[nt][1] = f2tf32(bs[c0 + 4 * BS_STRIDE]);
            }
#pragma unroll
            for (int mt = 0; mt < 4; mt++)
#pragma unroll
                for (int nt = 0; nt < 4; nt++)
                    mma_tf32(acc[mt][nt], af[mt], bf[nt]);
        }
        s ^= 1;
    }

    // ---- fused epilogue ----
    if (mode == 0) {
        const float alpha = *scal;
        const float oma = 1.0f - alpha;
#pragma unroll
        for (int mt = 0; mt < 4; mt++) {
#pragma unroll
            for (int nt = 0; nt < 4; nt++) {
                int row = rowBase + wm + mt * 16 + lg;
                int col = colBase + wn + nt * 8 + lr * 2;
                size_t off0 = (size_t)row * N + col;
                size_t off1 = off0 + (size_t)8 * N;
                float2 c0 = *reinterpret_cast<const float2*>(&Caux[off0]);
                float2 c1 = *reinterpret_cast<const float2*>(&Caux[off1]);
                float2 s0, s1;
                s0.x = oma * acc[mt][nt][0] + alpha * c0.x;
                s0.y = oma * acc[mt][nt][1] + alpha * c0.y;
                s1.x = oma * acc[mt][nt][2] + alpha * c1.x;
                s1.y = oma * acc[mt][nt][3] + alpha * c1.y;
                *reinterpret_cast<float2*>(&D0[off0]) = s0;
                *reinterpret_cast<float2*>(&D0[off1]) = s1;
                *reinterpret_cast<float2*>(&D1[off0]) = s0;
                *reinterpret_cast<float2*>(&D1[off1]) = s1;
            }
        }
    } else {
        const float lam = *scal;
        const float lv = (float)(*lptr);
        const float theta = logf(lam / lv + 1.0f);
        const float omt = 1.0f - theta;
#pragma unroll
        for (int mt = 0; mt < 4; mt++) {
#pragma unroll
            for (int nt = 0; nt < 4; nt++) {
                int row = rowBase + wm + mt * 16 + lg;
                int col = colBase + wn + nt * 8 + lr * 2;
                size_t off0 = (size_t)row * N + col;
                size_t off1 = off0 + (size_t)8 * N;
                float2 c0 = *reinterpret_cast<const float2*>(&Caux[off0]);
                float2 c1 = *reinterpret_cast<const float2*>(&Caux[off1]);
                float2 s0, s1;
                s0.x = theta * acc[mt][nt][0] + omt * c0.x;
                s0.y = theta * acc[mt][nt][1] + omt * c0.y;
                s1.x = theta * acc[mt][nt][2] + omt * c1.x;
                s1.y = theta * acc[mt][nt][3] + omt * c1.y;
                *reinterpret_cast<float2*>(&D0[off0]) = s0;
                *reinterpret_cast<float2*>(&D0[off1]) = s1;
            }
        }
    }
#undef LOAD_STAGE
}

// one block per agent row; 256 threads x 4 cols; warp-local RNG (no barrier)
__global__ void __launch_bounds__(256) whale_kernel(
    const float* __restrict__ posIn, float* __restrict__ posOut,
    int leaderIdx, float av, float twoa, float a2m1,
    u32 k1a, u32 k1b, u32 k2a, u32 k2b, u32 k3a, u32 k3b, u32 k4a, u32 k4b,
    u32 kba, u32 kbb)
{
    const int i = blockIdx.x;
    const int t = threadIdx.x;
    const int lane = t & 31;
    const int j0 = t * 4;

    // issue position/leader loads first (not fenced behind any barrier)
    const float4 pv  = *reinterpret_cast<const float4*>(&posIn[(size_t)i * DCOLS + j0]);
    const float4 lv4 = *reinterpret_cast<const float4*>(&posIn[(size_t)leaderIdx * DCOLS + j0]);

    // all lanes redundantly compute one of 4 draws; broadcast via shfl
    const int sel = lane & 3;
    u32 ka = (sel == 0) ? k1a : (sel == 1) ? k2a : (sel == 2) ? k3a : k4a;
    u32 kb = (sel == 0) ? k1b : (sel == 1) ? k2b : (sel == 2) ? k3b : k4b;
    float rv = bits01(dbits32(ka, kb, (u32)i));
    const float r1 = __shfl_sync(0xffffffffu, rv, 0);
    const float r2 = __shfl_sync(0xffffffffu, rv, 1);
    const float u3 = __shfl_sync(0xffffffffu, rv, 2);
    const float p  = __shfl_sync(0xffffffffu, rv, 3);

    const float A  = __fsub_rn(__fmul_rn(twoa, r1), av);
    const float C  = 2.0f * r2;
    const float lp = __fadd_rn(__fmul_rn(a2m1, u3), 1.0f);
    const float lower = key2f(g_mm[0]);
    const float upper = key2f(g_mm[1]);
    const int mode = (p < 0.5f) ? ((fabsf(A) >= 1.0f) ? 0 : 1) : 2;

    float pos[4] = {pv.x, pv.y, pv.z, pv.w};
    float led[4] = {lv4.x, lv4.y, lv4.z, lv4.w};
    float outv[4];

    if (mode == 0) {
#pragma unroll
        for (int q = 0; q < 4; q++) {
            u32 m = (u32)i * 1024u + (u32)(j0 + q);
            u32 bits = dbits32(kba, kbb, m);
            int ridx = (int)(bits & 8191u);
            float xr = __ldg(&posIn[(size_t)ridx * DCOLS + j0 + q]);
            outv[q] = fabsf(xr - A * fabsf(C * xr - pos[q]));
        }
    } else if (mode == 1) {
#pragma unroll
        for (int q = 0; q < 4; q++)
            outv[q] = fabsf(led[q] - A * fabsf(C * led[q] - pos[q]));
    } else {
        const float sp = expf(lp) * cosf(6.283185307179586f * lp);
#pragma unroll
        for (int q = 0; q < 4; q++)
            outv[q] = fabsf(fabsf(led[q] - pos[q]) * sp + led[q]);
    }
    float4 ov;
    ov.x = fminf(fmaxf(outv[0], lower), upper);
    ov.y = fminf(fmaxf(outv[1], lower), upper);
    ov.z = fminf(fmaxf(outv[2], lower), upper);
    ov.w = fminf(fmaxf(outv[3], lower), upper);
    *reinterpret_cast<float4*>(&posOut[(size_t)i * DCOLS + j0]) = ov;
}

// ---------------- host ----------------
extern "C" void kernel_launch(void* const* d_in, const int* in_sizes, int n_in,
                              void* d_out, int out_size) {
    (void)in_sizes; (void)n_in; (void)out_size;
    const float* input  = (const float*)d_in[0];
    const float* adj    = (const float*)d_in[1];
    const float* h0     = (const float*)d_in[2];
    const float* weight = (const float*)d_in[3];
    const float* lamda  = (const float*)d_in[4];
    const float* alpha  = (const float*)d_in[5];
    const int*   lint   = (const int*)d_in[6];
    float* out = (float*)d_out;

    float *support, *posA, *posB;
    cudaGetSymbolAddress((void**)&support, g_support);
    cudaGetSymbolAddress((void**)&posA, g_posA);
    cudaGetSymbolAddress((void**)&posB, g_posB);

    init_mm_kernel<<<1, 1>>>();

    dim3 gemm_grid(DCOLS / BN, NROWS / BM);
    // support/posA = (1-alpha)*(adj@input) + alpha*h0
    mma_gemm_kernel<<<gemm_grid, 256>>>(adj, input, DCOLS, KDIM, 0,
                                        h0, support, posA, alpha, nullptr);
    minmax_kernel<<<512, 256>>>();

    // ---- JAX RNG derivation for key(42), partitionable-threefry semantics ----
    const u32 B0 = 0u, B1 = 42u;
    u32 K00, K01, L0, L1;
    htf(B0, B1, 0u, 0u, &K00, &K01);  // k0
    htf(B0, B1, 0u, 1u, &L0, &L1);    // loop_key
    u32 lka, lkb;
    htf(K00, K01, 0u, 1u, &lka, &lkb);
    int leader = (int)(hbits32(lka, lkb, 0u) & 8191u);

    float* pin = posA;
    float* pout = posB;
    for (int it = 0; it < 10; it++) {
        u32 f0, f1;
        htf(L0, L1, 0u, (u32)it, &f0, &f1);  // fold_in(loop_key, it)
        u32 SK[6][2];
        for (int j = 0; j < 6; j++) htf(f0, f1, 0u, (u32)j, &SK[j][0], &SK[j][1]);
        u32 k1a = SK[0][0], k1b = SK[0][1];
        u32 k2a = SK[1][0], k2b = SK[1][1];
        u32 k3a = SK[2][0], k3b = SK[2][1];
        u32 k4a = SK[3][0], k4b = SK[3][1];
        u32 k5a = SK[4][0], k5b = SK[4][1];
        u32 k6a = SK[5][0], k6b = SK[5][1];
        u32 kba, kbb;
        htf(k5a, k5b, 0u, 1u, &kba, &kbb);
        u32 l6a, l6b;
        htf(k6a, k6b, 0u, 1u, &l6a, &l6b);
        int nextLeader = (int)(hbits32(l6a, l6b, 0u) & 8191u);

        const float itf = (float)it;
        volatile float tmul = itf * 0.2f;
        const float a = 2.0f - tmul;
        const float twoa = 2.0f * a;
        volatile float tmul2 = itf * (-0.1f);
        const float a2 = -1.0f + tmul2;
        const float a2m1 = a2 - 1.0f;

        whale_kernel<<<NROWS, 256>>>(pin, pout, leader, a, twoa, a2m1,
                                     k1a, k1b, k2a, k2b, k3a, k3b, k4a, k4b,
                                     kba, kbb);
        leader = nextLeader;
        float* tswap = pin; pin = pout; pout = tswap;
    }

    // out = theta*(pos@weight) + (1-theta)*support
    mma_gemm_kernel<<<gemm_grid, 256>>>(pin, weight, DCOLS, DCOLS, 1,
                                        support, out, nullptr, lamda, lint);
}